// round 14
// baseline (speedup 1.0000x reference)
#include <cuda_runtime.h>
#include <cuda_bf16.h>
#include <cstdint>

#define NA 50000
#define AFD 133
#define HID 128
#define NE 800000
#define NM 1024
#define KPAD 192
#define NT128 ((NA + 127) / 128)   // 391

#define RSTRIDE 144
#define WCHUNK 18432               // 128 rows * 144
#define GTHREADS 512

// ====================== helpers ======================
__device__ __forceinline__ uint32_t smem_u32(const void* p) {
    uint32_t a;
    asm("{ .reg .u64 t; cvta.to.shared.u64 t, %1; cvt.u32.u64 %0, t; }" : "=r"(a) : "l"(p));
    return a;
}
__device__ __forceinline__ void ldsm4(uint32_t* r, uint32_t addr) {
    asm volatile("ldmatrix.sync.aligned.m8n8.x4.shared.b16 {%0,%1,%2,%3}, [%4];"
                 : "=r"(r[0]), "=r"(r[1]), "=r"(r[2]), "=r"(r[3]) : "r"(addr));
}
__device__ __forceinline__ void mma16816(float* c, const uint32_t* a, const uint32_t* b) {
    asm volatile(
        "mma.sync.aligned.m16n8k16.row.col.f32.bf16.bf16.f32 "
        "{%0,%1,%2,%3}, {%4,%5,%6,%7}, {%8,%9}, {%0,%1,%2,%3};"
        : "+f"(c[0]), "+f"(c[1]), "+f"(c[2]), "+f"(c[3])
        : "r"(a[0]), "r"(a[1]), "r"(a[2]), "r"(a[3]), "r"(b[0]), "r"(b[1]));
}
__device__ __forceinline__ void cp_async16(uint32_t dst, const void* src, uint32_t bytes) {
    asm volatile("cp.async.cg.shared.global [%0], [%1], 16, %2;"
                 :: "r"(dst), "l"(src), "r"(bytes));
}
#define CP_COMMIT() asm volatile("cp.async.commit_group;" ::: "memory")
#define CP_WAIT0()  asm volatile("cp.async.wait_group 0;" ::: "memory")

__device__ __forceinline__ void split2(float v0, float v1, uint32_t& h, uint32_t& l) {
    __nv_bfloat16 h0 = __float2bfloat16(v0), h1 = __float2bfloat16(v1);
    __nv_bfloat16 l0 = __float2bfloat16(v0 - __bfloat162float(h0));
    __nv_bfloat16 l1 = __float2bfloat16(v1 - __bfloat162float(h1));
    h = ((uint32_t)__bfloat16_as_ushort(h1) << 16) | __bfloat16_as_ushort(h0);
    l = ((uint32_t)__bfloat16_as_ushort(l1) << 16) | __bfloat16_as_ushort(l0);
}

// ====================== scratch ======================
__device__ float g_x[NA * HID];
__device__ float g_agg[NA * HID];
__device__ __nv_bfloat16 g_fh[NA * KPAD], g_fl[NA * KPAD];
__device__ __nv_bfloat16 g_ah[NA * HID], g_al[NA * HID];
__device__ __nv_bfloat16 g_wfh[HID * KPAD], g_wfl[HID * KPAD];
__device__ __nv_bfloat16 g_w1h[3 * HID * HID], g_w1l[3 * HID * HID];
__device__ __nv_bfloat16 g_w2h[3 * HID * HID], g_w2l[3 * HID * HID];
__device__ int g_deg[NA];
__device__ int g_off[NA + 1];
__device__ int g_pos[NA];
__device__ int g_srclist[NE];
__device__ float g_sumA[2][HID];
__device__ float g_sumsqA[2][HID];

// ====================== conversions ======================
__global__ void convert_atoms_kernel(const float* __restrict__ f) {
    int i = blockIdx.x * blockDim.x + threadIdx.x;
    int total = NA * (KPAD / 2);
    if (i >= total) return;
    int row = i / (KPAD / 2), p = i % (KPAD / 2);
    int k = 2 * p;
    float v0 = (k < AFD) ? f[row * AFD + k] : 0.f;
    float v1 = (k + 1 < AFD) ? f[row * AFD + k + 1] : 0.f;
    uint32_t h, l;
    split2(v0, v1, h, l);
    ((uint32_t*)g_fh)[row * (KPAD / 2) + p] = h;
    ((uint32_t*)g_fl)[row * (KPAD / 2) + p] = l;
}

__global__ void prep_weights_kernel(const float* __restrict__ W_in,
                                    const float* __restrict__ W1,
                                    const float* __restrict__ W2) {
    int i = blockIdx.x * blockDim.x + threadIdx.x;
    int stride = gridDim.x * blockDim.x;
    for (int idx = i; idx < HID * KPAD; idx += stride) {
        int n = idx / KPAD, k = idx % KPAD;
        float v = (k < AFD) ? W_in[k * HID + n] : 0.f;
        __nv_bfloat16 h = __float2bfloat16(v);
        g_wfh[idx] = h;
        g_wfl[idx] = __float2bfloat16(v - __bfloat162float(h));
    }
    for (int idx = i; idx < 3 * HID * HID; idx += stride) {
        int d = idx / (HID * HID);
        int r = idx % (HID * HID);
        int n = r / HID, k = r % HID;
        float v1 = W1[d * HID * HID + k * HID + n];
        float v2 = W2[d * HID * HID + k * HID + n];
        __nv_bfloat16 h1 = __float2bfloat16(v1);
        g_w1h[idx] = h1;
        g_w1l[idx] = __float2bfloat16(v1 - __bfloat162float(h1));
        __nv_bfloat16 h2 = __float2bfloat16(v2);
        g_w2h[idx] = h2;
        g_w2l[idx] = __float2bfloat16(v2 - __bfloat162float(h2));
    }
}

// ====================== CSR build ======================
__global__ void zero_csr_kernel() {
    int i = blockIdx.x * blockDim.x + threadIdx.x;
    int stride = gridDim.x * blockDim.x;
    for (int k = i; k < NA; k += stride) { g_deg[k] = 0; g_pos[k] = 0; }
}
__global__ void count_kernel(const int* __restrict__ ei) {
    int e4 = blockIdx.x * blockDim.x + threadIdx.x;
    if (e4 < NE / 4) {
        int4 t = ((const int4*)(ei + NE))[e4];
        atomicAdd(&g_deg[t.x], 1);
        atomicAdd(&g_deg[t.y], 1);
        atomicAdd(&g_deg[t.z], 1);
        atomicAdd(&g_deg[t.w], 1);
    }
}
__global__ void scan_kernel() {
    __shared__ int sm[1024];
    int t = threadIdx.x;
    const int C = (NA + 1023) / 1024;
    int start = t * C;
    int end = min((t + 1) * C, NA);
    int s = 0;
    for (int i = start; i < end; i++) s += g_deg[i];
    sm[t] = s;
    __syncthreads();
    for (int d = 1; d < 1024; d <<= 1) {
        int v = (t >= d) ? sm[t - d] : 0;
        __syncthreads();
        sm[t] += v;
        __syncthreads();
    }
    int run = (t > 0) ? sm[t - 1] : 0;
    for (int i = start; i < end; i++) { g_off[i] = run; run += g_deg[i]; }
    if (start < NA && end == NA) g_off[NA] = run;
}
__global__ void fill_kernel(const int* __restrict__ ei) {
    int e4 = blockIdx.x * blockDim.x + threadIdx.x;
    if (e4 < NE / 4) {
        int4 t = ((const int4*)(ei + NE))[e4];
        int4 s = ((const int4*)ei)[e4];
        int sl;
        sl = atomicAdd(&g_pos[t.x], 1); g_srclist[g_off[t.x] + sl] = s.x;
        sl = atomicAdd(&g_pos[t.y], 1); g_srclist[g_off[t.y] + sl] = s.y;
        sl = atomicAdd(&g_pos[t.z], 1); g_srclist[g_off[t.z] + sl] = s.z;
        sl = atomicAdd(&g_pos[t.w], 1); g_srclist[g_off[t.w] + sl] = s.w;
    }
}

// ====================== gather (+fused BN/ReLU of previous depth) ==========
template <bool BN>
__global__ void gather_kernel(const float* __restrict__ src_arr,
                              const float* __restrict__ epsp, int d,
                              const float* __restrict__ gamma,
                              const float* __restrict__ beta,
                              int rslot, int zslot) {
    if (blockIdx.x == 0 && threadIdx.x < 2 * HID) {
        if (threadIdx.x < HID) g_sumA[zslot][threadIdx.x] = 0.f;
        else g_sumsqA[zslot][threadIdx.x - HID] = 0.f;
    }
    int gw = (blockIdx.x * blockDim.x + threadIdx.x) >> 5;
    int lane = threadIdx.x & 31;
    if (gw >= NA) return;

    float4 bsc = make_float4(0.f, 0.f, 0.f, 0.f), bsh = make_float4(0.f, 0.f, 0.f, 0.f);
    if (BN) {
        const float invN = 1.f / (float)NA;
        int c0 = lane * 4;
#pragma unroll
        for (int q = 0; q < 4; q++) {
            int c = c0 + q;
            float mean = g_sumA[rslot][c] * invN;
            float var = g_sumsqA[rslot][c] * invN - mean * mean;
            float sc = gamma[c] * rsqrtf(var + 1e-5f);
            float sh = beta[c] - mean * sc;
            ((float*)&bsc)[q] = sc;
            ((float*)&bsh)[q] = sh;
        }
    }
    float scale = 1.f + epsp[d];
    const float4* x4 = (const float4*)src_arr;

    auto loadrow = [&](int r) -> float4 {
        float4 v = x4[r * 32 + lane];
        if (BN) {
            v.x = fmaxf(fmaf(v.x, bsc.x, bsh.x), 0.f);
            v.y = fmaxf(fmaf(v.y, bsc.y, bsh.y), 0.f);
            v.z = fmaxf(fmaf(v.z, bsc.z, bsh.z), 0.f);
            v.w = fmaxf(fmaf(v.w, bsc.w, bsh.w), 0.f);
        }
        return v;
    };

    float4 acc = loadrow(gw);
    acc.x *= scale; acc.y *= scale; acc.z *= scale; acc.w *= scale;
    int j = g_off[gw];
    int e = g_off[gw + 1];
    for (; j + 4 <= e; j += 4) {
        int s0 = g_srclist[j], s1 = g_srclist[j + 1];
        int s2 = g_srclist[j + 2], s3 = g_srclist[j + 3];
        float4 v0 = loadrow(s0), v1 = loadrow(s1), v2 = loadrow(s2), v3 = loadrow(s3);
        acc.x += (v0.x + v1.x) + (v2.x + v3.x);
        acc.y += (v0.y + v1.y) + (v2.y + v3.y);
        acc.z += (v0.z + v1.z) + (v2.z + v3.z);
        acc.w += (v0.w + v1.w) + (v2.w + v3.w);
    }
    for (; j < e; j++) {
        float4 v = loadrow(g_srclist[j]);
        acc.x += v.x; acc.y += v.y; acc.z += v.z; acc.w += v.w;
    }
    uint32_t h01, l01, h23, l23;
    split2(acc.x, acc.y, h01, l01);
    split2(acc.z, acc.w, h23, l23);
    ((uint2*)g_ah)[gw * 32 + lane] = make_uint2(h01, h23);
    ((uint2*)g_al)[gw * 32 + lane] = make_uint2(l01, l23);
}

// ====================== input GEMM (KC=3, 128-row tiles, 512 thr) ==========
// x = relu(f @ W_in + b_in). 16 warps: 4M x 4N, warp tile 32x32 (m=2).
// Pass-major MMA order: dependency distance on each accumulator = 8.
__global__ __launch_bounds__(GTHREADS, 1) void gemm_in_kernel(
    const __nv_bfloat16* __restrict__ Ah, const __nv_bfloat16* __restrict__ Al,
    const __nv_bfloat16* __restrict__ Wh, const __nv_bfloat16* __restrict__ Wl,
    const float* __restrict__ bias, float* __restrict__ Cf) {
    extern __shared__ char smem[];
    const int K = 192;
    const uint32_t OFF_WH = 512;
    const uint32_t OFF_WL = 512 + 3 * WCHUNK;
    const uint32_t OFF_XH = 512 + 6 * WCHUNK;
    const uint32_t OFF_XL = OFF_XH + 3 * WCHUNK;
    const uint32_t sb = smem_u32(smem);
    int tid = threadIdx.x;
    int wid = tid >> 5, lane = tid & 31;
    int warpM = wid & 3, warpN = wid >> 2;

    float* bias_s = (float*)smem;
    if (tid < HID) bias_s[tid] = bias[tid];

    // W resident
    for (int e = tid; e < 6144; e += GTHREADS) {
        int m = e / 3072, q = e % 3072;
        int c = q >> 10, r = (q >> 3) & 127, p = q & 7;
        const __nv_bfloat16* src = m ? Wl : Wh;
        uint4 v = *(const uint4*)(src + r * K + c * 64 + p * 8);
        *(uint4*)(smem + (m ? OFF_WL : OFF_WH) + c * WCHUNK + r * RSTRIDE + p * 16) = v;
    }

    int aRow = warpM * 32 + (lane & 15);
    int aCol = (lane >> 4) * 8;
    int bRow = warpN * 32 + ((lane >> 4) * 8) + (lane & 7);
    int bCol = ((lane >> 3) & 1) * 8;

    for (int t = blockIdx.x; t < NT128; t += gridDim.x) {
        int row0 = t * 128;
        __syncthreads();    // X free (prev tile fully consumed)
#pragma unroll
        for (int e = tid; e < 6144; e += GTHREADS) {
            int m = e / 3072, q = e % 3072;
            int c = q >> 10, r = (q >> 3) & 127, p = q & 7;
            int grow = row0 + r;
            const __nv_bfloat16* src = m ? Al : Ah;
            int sg = grow < NA ? grow : NA - 1;
            uint32_t bytes = grow < NA ? 16u : 0u;
            uint32_t off = (m ? OFF_XL : OFF_XH) + c * WCHUNK + r * RSTRIDE + p * 16;
            cp_async16(sb + off, src + sg * K + c * 64 + p * 8, bytes);
        }
        CP_COMMIT();
        CP_WAIT0();
        __syncthreads();

        float acc[2][4][4];
#pragma unroll
        for (int mf = 0; mf < 2; mf++)
#pragma unroll
            for (int nf = 0; nf < 4; nf++)
#pragma unroll
                for (int r = 0; r < 4; r++) acc[mf][nf][r] = 0.f;
#pragma unroll
        for (int c = 0; c < 3; c++) {
#pragma unroll
            for (int kk = 0; kk < 4; kk++) {
                int k0 = kk * 16;
                uint32_t ah[2][4], al[2][4], wh[2][4], wl[2][4];
#pragma unroll
                for (int mf = 0; mf < 2; mf++) {
                    uint32_t ad = c * WCHUNK + (aRow + mf * 16) * RSTRIDE + (k0 + aCol) * 2;
                    ldsm4(ah[mf], sb + OFF_XH + ad);
                    ldsm4(al[mf], sb + OFF_XL + ad);
                }
#pragma unroll
                for (int nf2 = 0; nf2 < 2; nf2++) {
                    uint32_t wd = c * WCHUNK + (bRow + nf2 * 16) * RSTRIDE + (k0 + bCol) * 2;
                    ldsm4(wh[nf2], sb + OFF_WH + wd);
                    ldsm4(wl[nf2], sb + OFF_WL + wd);
                }
                // pass-major: 8 independent MMAs between reuses of any acc
#pragma unroll
                for (int mf = 0; mf < 2; mf++)
#pragma unroll
                    for (int nf = 0; nf < 4; nf++)
                        mma16816(acc[mf][nf], ah[mf], &wh[nf >> 1][(nf & 1) * 2]);
#pragma unroll
                for (int mf = 0; mf < 2; mf++)
#pragma unroll
                    for (int nf = 0; nf < 4; nf++)
                        mma16816(acc[mf][nf], ah[mf], &wl[nf >> 1][(nf & 1) * 2]);
#pragma unroll
                for (int mf = 0; mf < 2; mf++)
#pragma unroll
                    for (int nf = 0; nf < 4; nf++)
                        mma16816(acc[mf][nf], al[mf], &wh[nf >> 1][(nf & 1) * 2]);
            }
        }
#pragma unroll
        for (int mf = 0; mf < 2; mf++) {
            int r0 = row0 + warpM * 32 + mf * 16 + (lane >> 2);
#pragma unroll
            for (int half = 0; half < 2; half++) {
                int row = r0 + half * 8;
                if (row >= NA) continue;
#pragma unroll
                for (int nf = 0; nf < 4; nf++) {
                    int col = warpN * 32 + nf * 8 + 2 * (lane & 3);
                    float v0 = fmaxf(acc[mf][nf][half * 2 + 0] + bias_s[col], 0.f);
                    float v1 = fmaxf(acc[mf][nf][half * 2 + 1] + bias_s[col + 1], 0.f);
                    *(float2*)(Cf + row * HID + col) = make_float2(v0, v1);
                }
            }
        }
    }
}

// ====================== fused MLP (128-row tiles, 512 thr, m=2) ============
// agg@W1 -> relu -> @W2 (+stats). Y (h tile) aliases X (dead after pass1).
__global__ __launch_bounds__(GTHREADS, 1) void mlp_fused_kernel(
    const __nv_bfloat16* __restrict__ Ah, const __nv_bfloat16* __restrict__ Al,
    const __nv_bfloat16* __restrict__ W1h, const __nv_bfloat16* __restrict__ W1l,
    const __nv_bfloat16* __restrict__ W2h, const __nv_bfloat16* __restrict__ W2l,
    const float* __restrict__ b1, const float* __restrict__ b2,
    float* __restrict__ Cf, int slot) {
    extern __shared__ char smem[];
    const uint32_t OFF_W1H = 1024;
    const uint32_t OFF_W1L = 1024 + 2 * WCHUNK;
    const uint32_t OFF_W2H = 1024 + 4 * WCHUNK;
    const uint32_t OFF_W2L = 1024 + 6 * WCHUNK;
    const uint32_t OFF_XH = 1024 + 8 * WCHUNK;
    const uint32_t OFF_XL = OFF_XH + 2 * WCHUNK;
    const uint32_t sb = smem_u32(smem);
    int tid = threadIdx.x;
    int wid = tid >> 5, lane = tid & 31;
    int warpM = wid & 3, warpN = wid >> 2;

    float* b1_s = (float*)smem;
    float* b2_s = (float*)(smem + 512);
    if (tid < HID) { b1_s[tid] = b1[tid]; b2_s[tid] = b2[tid]; }

    for (int e = tid; e < 8192; e += GTHREADS) {
        int w2 = e / 4096, q2 = e % 4096;
        int m = q2 / 2048, q = q2 % 2048;
        int c = q >> 10, r = (q >> 3) & 127, p = q & 7;
        const __nv_bfloat16* src = w2 ? (m ? W2l : W2h) : (m ? W1l : W1h);
        uint32_t dst = w2 ? (m ? OFF_W2L : OFF_W2H) : (m ? OFF_W1L : OFF_W1H);
        uint4 v = *(const uint4*)(src + r * HID + c * 64 + p * 8);
        *(uint4*)(smem + dst + c * WCHUNK + r * RSTRIDE + p * 16) = v;
    }

    int aRow = warpM * 32 + (lane & 15);
    int aCol = (lane >> 4) * 8;
    int bRow = warpN * 32 + ((lane >> 4) * 8) + (lane & 7);
    int bCol = ((lane >> 3) & 1) * 8;

    float colSum[8], colSq[8];
#pragma unroll
    for (int j = 0; j < 8; j++) { colSum[j] = 0.f; colSq[j] = 0.f; }

    // one 128-wide GEMM pass over the 128-row tile (m=2, pass-major MMAs)
    auto pass = [&](uint32_t srcH, uint32_t srcL, uint32_t offWH, uint32_t offWL,
                    float acc[2][4][4]) {
#pragma unroll
        for (int mf = 0; mf < 2; mf++)
#pragma unroll
            for (int nf = 0; nf < 4; nf++)
#pragma unroll
                for (int r = 0; r < 4; r++) acc[mf][nf][r] = 0.f;
#pragma unroll
        for (int c = 0; c < 2; c++) {
#pragma unroll
            for (int kk = 0; kk < 4; kk++) {
                int k0 = kk * 16;
                uint32_t ah[2][4], al[2][4], wh[2][4], wl[2][4];
#pragma unroll
                for (int mf = 0; mf < 2; mf++) {
                    uint32_t ad = c * WCHUNK + (aRow + mf * 16) * RSTRIDE + (k0 + aCol) * 2;
                    ldsm4(ah[mf], sb + srcH + ad);
                    ldsm4(al[mf], sb + srcL + ad);
                }
#pragma unroll
                for (int nf2 = 0; nf2 < 2; nf2++) {
                    uint32_t wd = c * WCHUNK + (bRow + nf2 * 16) * RSTRIDE + (k0 + bCol) * 2;
                    ldsm4(wh[nf2], sb + offWH + wd);
                    ldsm4(wl[nf2], sb + offWL + wd);
                }
#pragma unroll
                for (int mf = 0; mf < 2; mf++)
#pragma unroll
                    for (int nf = 0; nf < 4; nf++)
                        mma16816(acc[mf][nf], ah[mf], &wh[nf >> 1][(nf & 1) * 2]);
#pragma unroll
                for (int mf = 0; mf < 2; mf++)
#pragma unroll
                    for (int nf = 0; nf < 4; nf++)
                        mma16816(acc[mf][nf], ah[mf], &wl[nf >> 1][(nf & 1) * 2]);
#pragma unroll
                for (int mf = 0; mf < 2; mf++)
#pragma unroll
                    for (int nf = 0; nf < 4; nf++)
                        mma16816(acc[mf][nf], al[mf], &wh[nf >> 1][(nf & 1) * 2]);
            }
        }
    };

    for (int t = blockIdx.x; t < NT128; t += gridDim.x) {
        int row0 = t * 128;
        __syncthreads();    // X/Y region free (prev tile pass2 done)
#pragma unroll
        for (int e = tid; e < 4096; e += GTHREADS) {
            int m = e >> 11, q = e & 2047;
            int c = q >> 10, r = (q >> 3) & 127, p = q & 7;
            int grow = row0 + r;
            const __nv_bfloat16* src = m ? Al : Ah;
            int sg = grow < NA ? grow : NA - 1;
            uint32_t bytes = grow < NA ? 16u : 0u;
            uint32_t off = (m ? OFF_XL : OFF_XH) + c * WCHUNK + r * RSTRIDE + p * 16;
            cp_async16(sb + off, src + sg * HID + c * 64 + p * 8, bytes);
        }
        CP_COMMIT();
        CP_WAIT0();
        __syncthreads();    // X ready

        float acc[2][4][4];
        pass(OFF_XH, OFF_XL, OFF_W1H, OFF_W1L, acc);
        __syncthreads();    // all warps done reading X

        // epilogue1: h = relu(acc + b1) -> Y (aliases X)
#pragma unroll
        for (int mf = 0; mf < 2; mf++) {
            int lr0 = warpM * 32 + mf * 16 + (lane >> 2);
#pragma unroll
            for (int half = 0; half < 2; half++) {
                int lrow = lr0 + half * 8;
#pragma unroll
                for (int nf = 0; nf < 4; nf++) {
                    int col = warpN * 32 + nf * 8 + 2 * (lane & 3);
                    float v0 = fmaxf(acc[mf][nf][half * 2 + 0] + b1_s[col], 0.f);
                    float v1 = fmaxf(acc[mf][nf][half * 2 + 1] + b1_s[col + 1], 0.f);
                    uint32_t h, l;
                    split2(v0, v1, h, l);
                    int c = col >> 6, cc = col & 63;
                    uint32_t off = c * WCHUNK + lrow * RSTRIDE + cc * 2;
                    *(uint32_t*)(smem + OFF_XH + off) = h;
                    *(uint32_t*)(smem + OFF_XL + off) = l;
                }
            }
        }
        __syncthreads();    // Y complete

        pass(OFF_XH, OFF_XL, OFF_W2H, OFF_W2L, acc);

        // epilogue2: out = acc + b2, accumulate stats, write fp32
#pragma unroll
        for (int mf = 0; mf < 2; mf++) {
            int r0 = row0 + warpM * 32 + mf * 16 + (lane >> 2);
#pragma unroll
            for (int half = 0; half < 2; half++) {
                int row = r0 + half * 8;
                if (row >= NA) continue;
#pragma unroll
                for (int nf = 0; nf < 4; nf++) {
                    int col = warpN * 32 + nf * 8 + 2 * (lane & 3);
                    float v0 = acc[mf][nf][half * 2 + 0] + b2_s[col];
                    float v1 = acc[mf][nf][half * 2 + 1] + b2_s[col + 1];
                    colSum[nf * 2] += v0;     colSq[nf * 2] += v0 * v0;
                    colSum[nf * 2 + 1] += v1; colSq[nf * 2 + 1] += v1 * v1;
                    *(float2*)(Cf + row * HID + col) = make_float2(v0, v1);
                }
            }
        }
    }

    // stats reduction
    __syncthreads();
    float* rs = (float*)smem;
    if (tid < 256) rs[tid] = 0.f;
    __syncthreads();
#pragma unroll
    for (int j = 0; j < 8; j++) {
        int col = warpN * 32 + (j >> 1) * 8 + 2 * (lane & 3) + (j & 1);
        atomicAdd(&rs[col], colSum[j]);
        atomicAdd(&rs[128 + col], colSq[j]);
    }
    __syncthreads();
    if (tid < 128) {
        atomicAdd(&g_sumA[slot][tid], rs[tid]);
        atomicAdd(&g_sumsqA[slot][tid], rs[128 + tid]);
    }
}

// ====================== pooling (+fused BN/ReLU of last depth) =============
__global__ void pool_kernel(const int* __restrict__ seg, float* __restrict__ out,
                            const float* __restrict__ gamma,
                            const float* __restrict__ beta, int slot) {
    int m = blockIdx.x;
    int t = threadIdx.x;
    const float invN = 1.f / (float)NA;
    float mean = g_sumA[slot][t] * invN;
    float var = g_sumsqA[slot][t] * invN - mean * mean;
    float sc = gamma[t] * rsqrtf(var + 1e-5f);
    float sh = beta[t] - mean * sc;
    int lo = 0, hi = NA;
    while (lo < hi) { int mid = (lo + hi) >> 1; if (seg[mid] < m) lo = mid + 1; else hi = mid; }
    int start = lo;
    hi = NA;
    while (lo < hi) { int mid = (lo + hi) >> 1; if (seg[mid] < m + 1) lo = mid + 1; else hi = mid; }
    int end = lo;
    float s = 0.f;
    for (int a = start; a < end; a++)
        s += fmaxf(fmaf(g_agg[a * HID + t], sc, sh), 0.f);
    int cnt = end - start;
    out[m * HID + t] = (cnt > 0) ? s / (float)cnt : 0.f;
}

// ====================== launch ======================
extern "C" void kernel_launch(void* const* d_in, const int* in_sizes, int n_in,
                              void* d_out, int out_size) {
    const float* f_atoms = (const float*)d_in[0];
    const float* W_in    = (const float*)d_in[1];
    const float* b_in    = (const float*)d_in[2];
    const float* W1      = (const float*)d_in[3];
    const float* b1      = (const float*)d_in[4];
    const float* W2      = (const float*)d_in[5];
    const float* b2      = (const float*)d_in[6];
    const float* gamma   = (const float*)d_in[7];
    const float* beta    = (const float*)d_in[8];
    const float* epsp    = (const float*)d_in[9];
    const int*   ei      = (const int*)d_in[10];
    const int*   seg     = (const int*)d_in[11];
    float* out = (float*)d_out;

    float *p_x, *p_agg;
    __nv_bfloat16 *p_fh, *p_fl, *p_ah, *p_al;
    __nv_bfloat16 *p_wfh, *p_wfl, *p_w1h, *p_w1l, *p_w2h, *p_w2l;
    cudaGetSymbolAddress((void**)&p_x, g_x);
    cudaGetSymbolAddress((void**)&p_agg, g_agg);
    cudaGetSymbolAddress((void**)&p_fh, g_fh);
    cudaGetSymbolAddress((void**)&p_fl, g_fl);
    cudaGetSymbolAddress((void**)&p_ah, g_ah);
    cudaGetSymbolAddress((void**)&p_al, g_al);
    cudaGetSymbolAddress((void**)&p_wfh, g_wfh);
    cudaGetSymbolAddress((void**)&p_wfl, g_wfl);
    cudaGetSymbolAddress((void**)&p_w1h, g_w1h);
    cudaGetSymbolAddress((void**)&p_w1l, g_w1l);
    cudaGetSymbolAddress((void**)&p_w2h, g_w2h);
    cudaGetSymbolAddress((void**)&p_w2l, g_w2l);

    const int SMEM_IN  = 512 + 12 * WCHUNK;   // 221696
    const int SMEM_MLP = 1024 + 12 * WCHUNK;  // 222208
    cudaFuncSetAttribute(gemm_in_kernel,
                         cudaFuncAttributeMaxDynamicSharedMemorySize, SMEM_IN);
    cudaFuncSetAttribute(mlp_fused_kernel,
                         cudaFuncAttributeMaxDynamicSharedMemorySize, SMEM_MLP);

    const int EDGE4_BLOCKS = (NE / 4 + 255) / 256;

    prep_weights_kernel<<<96, 256>>>(W_in, W1, W2);
    convert_atoms_kernel<<<(NA * (KPAD / 2) + 255) / 256, 256>>>(f_atoms);
    zero_csr_kernel<<<98, 1024>>>();
    gemm_in_kernel<<<148, GTHREADS, SMEM_IN>>>(p_fh, p_fl, p_wfh, p_wfl, b_in, p_x);
    count_kernel<<<EDGE4_BLOCKS, 256>>>(ei);
    scan_kernel<<<1, 1024>>>();
    fill_kernel<<<EDGE4_BLOCKS, 256>>>(ei);

    for (int d = 0; d < 3; d++) {
        int rslot = (d + 1) & 1;
        int zslot = d & 1;
        if (d == 0)
            gather_kernel<false><<<(NA + 7) / 8, 256>>>(p_x, epsp, d, nullptr, nullptr, 0, zslot);
        else
            gather_kernel<true><<<(NA + 7) / 8, 256>>>(p_agg, epsp, d,
                gamma + (d - 1) * HID, beta + (d - 1) * HID, rslot, zslot);
        mlp_fused_kernel<<<148, GTHREADS, SMEM_MLP>>>(
            p_ah, p_al,
            p_w1h + d * HID * HID, p_w1l + d * HID * HID,
            p_w2h + d * HID * HID, p_w2l + d * HID * HID,
            b1 + d * HID, b2 + d * HID, p_agg, zslot);
    }

    pool_kernel<<<NM, HID>>>(seg, out, gamma + 2 * HID, beta + 2 * HID, 0);
}

// round 15
// speedup vs baseline: 1.0087x; 1.0087x over previous
#include <cuda_runtime.h>
#include <cuda_bf16.h>
#include <cuda_fp16.h>
#include <cstdint>

#define NA 50000
#define AFD 133
#define HID 128
#define NE 800000
#define NM 1024
#define KPAD 192
#define NT64 ((NA + 63) / 64)     // 782

#define RSTRIDE 144
#define WCHUNK 18432               // 128 rows * 144
#define C64 9216                   // 64 rows * 144
#define GTHREADS 512

// ====================== helpers ======================
__device__ __forceinline__ uint32_t smem_u32(const void* p) {
    uint32_t a;
    asm("{ .reg .u64 t; cvta.to.shared.u64 t, %1; cvt.u32.u64 %0, t; }" : "=r"(a) : "l"(p));
    return a;
}
__device__ __forceinline__ void ldsm4(uint32_t* r, uint32_t addr) {
    asm volatile("ldmatrix.sync.aligned.m8n8.x4.shared.b16 {%0,%1,%2,%3}, [%4];"
                 : "=r"(r[0]), "=r"(r[1]), "=r"(r[2]), "=r"(r[3]) : "r"(addr));
}
__device__ __forceinline__ void mma16816(float* c, const uint32_t* a, const uint32_t* b) {
    asm volatile(
        "mma.sync.aligned.m16n8k16.row.col.f32.bf16.bf16.f32 "
        "{%0,%1,%2,%3}, {%4,%5,%6,%7}, {%8,%9}, {%0,%1,%2,%3};"
        : "+f"(c[0]), "+f"(c[1]), "+f"(c[2]), "+f"(c[3])
        : "r"(a[0]), "r"(a[1]), "r"(a[2]), "r"(a[3]), "r"(b[0]), "r"(b[1]));
}
__device__ __forceinline__ void cp_async16(uint32_t dst, const void* src, uint32_t bytes) {
    asm volatile("cp.async.cg.shared.global [%0], [%1], 16, %2;"
                 :: "r"(dst), "l"(src), "r"(bytes));
}
#define CP_COMMIT() asm volatile("cp.async.commit_group;" ::: "memory")
#define CP_WAIT0()  asm volatile("cp.async.wait_group 0;" ::: "memory")

__device__ __forceinline__ void split2(float v0, float v1, uint32_t& h, uint32_t& l) {
    __nv_bfloat16 h0 = __float2bfloat16(v0), h1 = __float2bfloat16(v1);
    __nv_bfloat16 l0 = __float2bfloat16(v0 - __bfloat162float(h0));
    __nv_bfloat16 l1 = __float2bfloat16(v1 - __bfloat162float(h1));
    h = ((uint32_t)__bfloat16_as_ushort(h1) << 16) | __bfloat16_as_ushort(h0);
    l = ((uint32_t)__bfloat16_as_ushort(l1) << 16) | __bfloat16_as_ushort(l0);
}

// ====================== scratch ======================
__device__ __half g_xh[NA * HID];          // fp16 activations (gather input d=0)
__device__ __half g_aggh[NA * HID];        // fp16 gemm2 output (gather d>=1, pool)
__device__ __nv_bfloat16 g_fh[NA * KPAD], g_fl[NA * KPAD];
__device__ __nv_bfloat16 g_ah[NA * HID], g_al[NA * HID];
__device__ __nv_bfloat16 g_wfh[HID * KPAD], g_wfl[HID * KPAD];
__device__ __nv_bfloat16 g_w1h[3 * HID * HID], g_w1l[3 * HID * HID];
__device__ __nv_bfloat16 g_w2h[3 * HID * HID], g_w2l[3 * HID * HID];
__device__ int g_deg[NA];
__device__ int g_off[NA + 1];
__device__ int g_pos[NA];
__device__ int g_srclist[NE];
__device__ float g_sumA[2][HID];
__device__ float g_sumsqA[2][HID];

// ====================== conversions ======================
__global__ void convert_atoms_kernel(const float* __restrict__ f) {
    int i = blockIdx.x * blockDim.x + threadIdx.x;
    int total = NA * (KPAD / 2);
    if (i >= total) return;
    int row = i / (KPAD / 2), p = i % (KPAD / 2);
    int k = 2 * p;
    float v0 = (k < AFD) ? f[row * AFD + k] : 0.f;
    float v1 = (k + 1 < AFD) ? f[row * AFD + k + 1] : 0.f;
    uint32_t h, l;
    split2(v0, v1, h, l);
    ((uint32_t*)g_fh)[row * (KPAD / 2) + p] = h;
    ((uint32_t*)g_fl)[row * (KPAD / 2) + p] = l;
}

__global__ void prep_weights_kernel(const float* __restrict__ W_in,
                                    const float* __restrict__ W1,
                                    const float* __restrict__ W2) {
    int i = blockIdx.x * blockDim.x + threadIdx.x;
    int stride = gridDim.x * blockDim.x;
    for (int idx = i; idx < HID * KPAD; idx += stride) {
        int n = idx / KPAD, k = idx % KPAD;
        float v = (k < AFD) ? W_in[k * HID + n] : 0.f;
        __nv_bfloat16 h = __float2bfloat16(v);
        g_wfh[idx] = h;
        g_wfl[idx] = __float2bfloat16(v - __bfloat162float(h));
    }
    for (int idx = i; idx < 3 * HID * HID; idx += stride) {
        int d = idx / (HID * HID);
        int r = idx % (HID * HID);
        int n = r / HID, k = r % HID;
        float v1 = W1[d * HID * HID + k * HID + n];
        float v2 = W2[d * HID * HID + k * HID + n];
        __nv_bfloat16 h1 = __float2bfloat16(v1);
        g_w1h[idx] = h1;
        g_w1l[idx] = __float2bfloat16(v1 - __bfloat162float(h1));
        __nv_bfloat16 h2 = __float2bfloat16(v2);
        g_w2h[idx] = h2;
        g_w2l[idx] = __float2bfloat16(v2 - __bfloat162float(h2));
    }
}

// ====================== CSR build ======================
__global__ void zero_csr_kernel() {
    int i = blockIdx.x * blockDim.x + threadIdx.x;
    int stride = gridDim.x * blockDim.x;
    for (int k = i; k < NA; k += stride) { g_deg[k] = 0; g_pos[k] = 0; }
}
__global__ void count_kernel(const int* __restrict__ ei) {
    int e4 = blockIdx.x * blockDim.x + threadIdx.x;
    if (e4 < NE / 4) {
        int4 t = ((const int4*)(ei + NE))[e4];
        atomicAdd(&g_deg[t.x], 1);
        atomicAdd(&g_deg[t.y], 1);
        atomicAdd(&g_deg[t.z], 1);
        atomicAdd(&g_deg[t.w], 1);
    }
}
__global__ void scan_kernel() {
    __shared__ int sm[1024];
    int t = threadIdx.x;
    const int C = (NA + 1023) / 1024;
    int start = t * C;
    int end = min((t + 1) * C, NA);
    int s = 0;
    for (int i = start; i < end; i++) s += g_deg[i];
    sm[t] = s;
    __syncthreads();
    for (int d = 1; d < 1024; d <<= 1) {
        int v = (t >= d) ? sm[t - d] : 0;
        __syncthreads();
        sm[t] += v;
        __syncthreads();
    }
    int run = (t > 0) ? sm[t - 1] : 0;
    for (int i = start; i < end; i++) { g_off[i] = run; run += g_deg[i]; }
    if (start < NA && end == NA) g_off[NA] = run;
}
__global__ void fill_kernel(const int* __restrict__ ei) {
    int e4 = blockIdx.x * blockDim.x + threadIdx.x;
    if (e4 < NE / 4) {
        int4 t = ((const int4*)(ei + NE))[e4];
        int4 s = ((const int4*)ei)[e4];
        int sl;
        sl = atomicAdd(&g_pos[t.x], 1); g_srclist[g_off[t.x] + sl] = s.x;
        sl = atomicAdd(&g_pos[t.y], 1); g_srclist[g_off[t.y] + sl] = s.y;
        sl = atomicAdd(&g_pos[t.z], 1); g_srclist[g_off[t.z] + sl] = s.z;
        sl = atomicAdd(&g_pos[t.w], 1); g_srclist[g_off[t.w] + sl] = s.w;
    }
}

// ====================== gather (fp16 rows, +fused BN/ReLU) =================
// reads fp16 rows (256 B/row); BN: v <- relu(v*sc + sh).
// acc = sum_nbr v[src] + (1+eps)*v[self]; writes bf16 hi/lo for GEMM1.
template <bool BN>
__global__ void gather_kernel(const __half* __restrict__ src_h,
                              const float* __restrict__ epsp, int d,
                              const float* __restrict__ gamma,
                              const float* __restrict__ beta,
                              int rslot, int zslot) {
    if (blockIdx.x == 0 && threadIdx.x < 2 * HID) {
        if (threadIdx.x < HID) g_sumA[zslot][threadIdx.x] = 0.f;
        else g_sumsqA[zslot][threadIdx.x - HID] = 0.f;
    }
    int gw = (blockIdx.x * blockDim.x + threadIdx.x) >> 5;
    int lane = threadIdx.x & 31;
    if (gw >= NA) return;

    float4 bsc = make_float4(1.f, 1.f, 1.f, 1.f), bsh = make_float4(0.f, 0.f, 0.f, 0.f);
    if (BN) {
        const float invN = 1.f / (float)NA;
        int c0 = lane * 4;
#pragma unroll
        for (int q = 0; q < 4; q++) {
            int c = c0 + q;
            float mean = g_sumA[rslot][c] * invN;
            float var = g_sumsqA[rslot][c] * invN - mean * mean;
            float sc = gamma[c] * rsqrtf(var + 1e-5f);
            float sh = beta[c] - mean * sc;
            ((float*)&bsc)[q] = sc;
            ((float*)&bsh)[q] = sh;
        }
    }
    float scale = 1.f + epsp[d];
    const uint2* x2 = (const uint2*)src_h;   // 4 halves per lane (8 B)

    auto loadrow = [&](int r) -> float4 {
        uint2 u = x2[r * 32 + lane];
        float2 f0 = __half22float2(*(__half2*)&u.x);
        float2 f1 = __half22float2(*(__half2*)&u.y);
        float4 v = make_float4(f0.x, f0.y, f1.x, f1.y);
        if (BN) {
            v.x = fmaxf(fmaf(v.x, bsc.x, bsh.x), 0.f);
            v.y = fmaxf(fmaf(v.y, bsc.y, bsh.y), 0.f);
            v.z = fmaxf(fmaf(v.z, bsc.z, bsh.z), 0.f);
            v.w = fmaxf(fmaf(v.w, bsc.w, bsh.w), 0.f);
        }
        return v;
    };

    float4 acc = loadrow(gw);
    acc.x *= scale; acc.y *= scale; acc.z *= scale; acc.w *= scale;
    int j = g_off[gw];
    int e = g_off[gw + 1];
    for (; j + 4 <= e; j += 4) {
        int s0 = g_srclist[j], s1 = g_srclist[j + 1];
        int s2 = g_srclist[j + 2], s3 = g_srclist[j + 3];
        float4 v0 = loadrow(s0), v1 = loadrow(s1), v2 = loadrow(s2), v3 = loadrow(s3);
        acc.x += (v0.x + v1.x) + (v2.x + v3.x);
        acc.y += (v0.y + v1.y) + (v2.y + v3.y);
        acc.z += (v0.z + v1.z) + (v2.z + v3.z);
        acc.w += (v0.w + v1.w) + (v2.w + v3.w);
    }
    for (; j < e; j++) {
        float4 v = loadrow(g_srclist[j]);
        acc.x += v.x; acc.y += v.y; acc.z += v.z; acc.w += v.w;
    }
    uint32_t h01, l01, h23, l23;
    split2(acc.x, acc.y, h01, l01);
    split2(acc.z, acc.w, h23, l23);
    ((uint2*)g_ah)[gw * 32 + lane] = make_uint2(h01, h23);
    ((uint2*)g_al)[gw * 32 + lane] = make_uint2(l01, l23);
}

// ====================== input GEMM (KC=3, 64-row tiles, DB, 512 thr) =======
// x = relu(f @ W_in + b_in) -> fp16. 16 warps: 4M x 4N, warp tile 16x32.
__global__ __launch_bounds__(GTHREADS, 1) void gemm_in_kernel(
    const __nv_bfloat16* __restrict__ Ah, const __nv_bfloat16* __restrict__ Al,
    const __nv_bfloat16* __restrict__ Wh, const __nv_bfloat16* __restrict__ Wl,
    const float* __restrict__ bias, __half* __restrict__ Ch16) {
    extern __shared__ char smem[];
    const int K = 192;
    const uint32_t OFF_WH = 512;
    const uint32_t OFF_WL = 512 + 3 * WCHUNK;        // 55808
    const uint32_t OFF_A = 512 + 6 * WCHUNK;         // 111104
    // buf b (0/1), part m (0=h,1=l): OFF_A + b*55296 + m*27648
    const uint32_t sb = smem_u32(smem);
    int tid = threadIdx.x;
    int wid = tid >> 5, lane = tid & 31;
    int warpM = wid & 3, warpN = wid >> 2;

    float* bias_s = (float*)smem;
    if (tid < HID) bias_s[tid] = bias[tid];

    // W resident (128-row chunks, KC=3)
    for (int e = tid; e < 6144; e += GTHREADS) {
        int m = e / 3072, q = e % 3072;
        int c = q >> 10, r = (q >> 3) & 127, p = q & 7;
        const __nv_bfloat16* src = m ? Wl : Wh;
        uint4 v = *(const uint4*)(src + r * K + c * 64 + p * 8);
        *(uint4*)(smem + (m ? OFF_WL : OFF_WH) + c * WCHUNK + r * RSTRIDE + p * 16) = v;
    }

    int aRow = warpM * 16 + (lane & 15);
    int aCol = (lane >> 4) * 8;
    int bRow = warpN * 32 + ((lane >> 4) * 8) + (lane & 7);
    int bCol = ((lane >> 3) & 1) * 8;

    auto issue_tile = [&](int row0, int buf) {
#pragma unroll
        for (int e = tid; e < 3072; e += GTHREADS) {
            int m = e / 1536, q = e % 1536;
            int c = q >> 9, r = (q >> 3) & 63, p = q & 7;
            int grow = row0 + r;
            const __nv_bfloat16* src = m ? Al : Ah;
            int sg = grow < NA ? grow : NA - 1;
            uint32_t bytes = grow < NA ? 16u : 0u;
            uint32_t off = OFF_A + buf * 55296 + m * 27648 + c * C64 + r * RSTRIDE + p * 16;
            cp_async16(sb + off, src + sg * K + c * 64 + p * 8, bytes);
        }
        CP_COMMIT();
    };

    issue_tile(blockIdx.x * 64, 0);
    int cur = 0;
    for (int t = blockIdx.x; t < NT64; t += gridDim.x) {
        CP_WAIT0();
        __syncthreads();
        int next = t + gridDim.x;
        if (next < NT64) issue_tile(next * 64, cur ^ 1);

        uint32_t offH = OFF_A + cur * 55296;
        uint32_t offL = offH + 27648;
        float acc[4][4];
#pragma unroll
        for (int nf = 0; nf < 4; nf++)
#pragma unroll
            for (int r = 0; r < 4; r++) acc[nf][r] = 0.f;
#pragma unroll
        for (int c = 0; c < 3; c++) {
#pragma unroll
            for (int kk = 0; kk < 4; kk++) {
                int k0 = kk * 16;
                uint32_t ah[4], al[4], wh[2][4], wl[2][4];
                uint32_t ad = c * C64 + aRow * RSTRIDE + (k0 + aCol) * 2;
                ldsm4(ah, sb + offH + ad);
                ldsm4(al, sb + offL + ad);
#pragma unroll
                for (int nf2 = 0; nf2 < 2; nf2++) {
                    uint32_t wd = c * WCHUNK + (bRow + nf2 * 16) * RSTRIDE + (k0 + bCol) * 2;
                    ldsm4(wh[nf2], sb + OFF_WH + wd);
                    ldsm4(wl[nf2], sb + OFF_WL + wd);
                }
#pragma unroll
                for (int nf = 0; nf < 4; nf++)
                    mma16816(acc[nf], ah, &wh[nf >> 1][(nf & 1) * 2]);
#pragma unroll
                for (int nf = 0; nf < 4; nf++)
                    mma16816(acc[nf], ah, &wl[nf >> 1][(nf & 1) * 2]);
#pragma unroll
                for (int nf = 0; nf < 4; nf++)
                    mma16816(acc[nf], al, &wh[nf >> 1][(nf & 1) * 2]);
            }
        }
        int r0 = t * 64 + warpM * 16 + (lane >> 2);
#pragma unroll
        for (int half = 0; half < 2; half++) {
            int row = r0 + half * 8;
            if (row >= NA) continue;
#pragma unroll
            for (int nf = 0; nf < 4; nf++) {
                int col = warpN * 32 + nf * 8 + 2 * (lane & 3);
                float v0 = fmaxf(acc[nf][half * 2 + 0] + bias_s[col], 0.f);
                float v1 = fmaxf(acc[nf][half * 2 + 1] + bias_s[col + 1], 0.f);
                __half2 p = __floats2half2_rn(v0, v1);
                *(uint32_t*)(Ch16 + row * HID + col) = *(uint32_t*)&p;
            }
        }
        cur ^= 1;
    }
}

// ====================== fused MLP (64-row tiles, DB X, Y aliases X) ========
// agg@W1 -> relu -> @W2 (+stats). Output agg fp16.
__global__ __launch_bounds__(GTHREADS, 1) void mlp_fused_kernel(
    const __nv_bfloat16* __restrict__ Ah, const __nv_bfloat16* __restrict__ Al,
    const __nv_bfloat16* __restrict__ W1h, const __nv_bfloat16* __restrict__ W1l,
    const __nv_bfloat16* __restrict__ W2h, const __nv_bfloat16* __restrict__ W2l,
    const float* __restrict__ b1, const float* __restrict__ b2,
    __half* __restrict__ C16, int slot) {
    extern __shared__ char smem[];
    const uint32_t OFF_W1H = 1024;
    const uint32_t OFF_W1L = 1024 + 2 * WCHUNK;      // 37888
    const uint32_t OFF_W2H = 1024 + 4 * WCHUNK;      // 74752
    const uint32_t OFF_W2L = 1024 + 6 * WCHUNK;      // 111616
    const uint32_t OFF_X = 1024 + 8 * WCHUNK;        // 148480
    // buf b (0/1), part m (0=h,1=l), chunk c: OFF_X + b*36864 + m*18432 + c*9216
    const uint32_t sb = smem_u32(smem);
    int tid = threadIdx.x;
    int wid = tid >> 5, lane = tid & 31;
    int warpM = wid & 3, warpN = wid >> 2;

    float* b1_s = (float*)smem;
    float* b2_s = (float*)(smem + 512);
    if (tid < HID) { b1_s[tid] = b1[tid]; b2_s[tid] = b2[tid]; }

    // W1 + W2 resident (128-row chunks, KC=2 each)
    for (int e = tid; e < 8192; e += GTHREADS) {
        int w2 = e / 4096, q2 = e % 4096;
        int m = q2 / 2048, q = q2 % 2048;
        int c = q >> 10, r = (q >> 3) & 127, p = q & 7;
        const __nv_bfloat16* src = w2 ? (m ? W2l : W2h) : (m ? W1l : W1h);
        uint32_t dst = w2 ? (m ? OFF_W2L : OFF_W2H) : (m ? OFF_W1L : OFF_W1H);
        uint4 v = *(const uint4*)(src + r * HID + c * 64 + p * 8);
        *(uint4*)(smem + dst + c * WCHUNK + r * RSTRIDE + p * 16) = v;
    }

    int aRow = warpM * 16 + (lane & 15);
    int aCol = (lane >> 4) * 8;
    int bRow = warpN * 32 + ((lane >> 4) * 8) + (lane & 7);
    int bCol = ((lane >> 3) & 1) * 8;

    float colSum[8], colSq[8];
#pragma unroll
    for (int j = 0; j < 8; j++) { colSum[j] = 0.f; colSq[j] = 0.f; }

    auto issue_tile = [&](int row0, int buf) {
#pragma unroll
        for (int e = tid; e < 2048; e += GTHREADS) {
            int m = e >> 10, q = e & 1023;
            int c = q >> 9, r = (q >> 3) & 63, p = q & 7;
            int grow = row0 + r;
            const __nv_bfloat16* src = m ? Al : Ah;
            int sg = grow < NA ? grow : NA - 1;
            uint32_t bytes = grow < NA ? 16u : 0u;
            uint32_t off = OFF_X + buf * 36864 + m * 18432 + c * C64 + r * RSTRIDE + p * 16;
            cp_async16(sb + off, src + sg * HID + c * 64 + p * 8, bytes);
        }
        CP_COMMIT();
    };

    // one 128-wide GEMM pass over a 64-row tile
    auto pass = [&](uint32_t srcH, uint32_t srcL, uint32_t offWH, uint32_t offWL,
                    float acc[4][4]) {
#pragma unroll
        for (int nf = 0; nf < 4; nf++)
#pragma unroll
            for (int r = 0; r < 4; r++) acc[nf][r] = 0.f;
#pragma unroll
        for (int c = 0; c < 2; c++) {
#pragma unroll
            for (int kk = 0; kk < 4; kk++) {
                int k0 = kk * 16;
                uint32_t ah[4], al[4], wh[2][4], wl[2][4];
                uint32_t ad = c * C64 + aRow * RSTRIDE + (k0 + aCol) * 2;
                ldsm4(ah, sb + srcH + ad);
                ldsm4(al, sb + srcL + ad);
#pragma unroll
                for (int nf2 = 0; nf2 < 2; nf2++) {
                    uint32_t wd = c * WCHUNK + (bRow + nf2 * 16) * RSTRIDE + (k0 + bCol) * 2;
                    ldsm4(wh[nf2], sb + offWH + wd);
                    ldsm4(wl[nf2], sb + offWL + wd);
                }
#pragma unroll
                for (int nf = 0; nf < 4; nf++)
                    mma16816(acc[nf], ah, &wh[nf >> 1][(nf & 1) * 2]);
#pragma unroll
                for (int nf = 0; nf < 4; nf++)
                    mma16816(acc[nf], ah, &wl[nf >> 1][(nf & 1) * 2]);
#pragma unroll
                for (int nf = 0; nf < 4; nf++)
                    mma16816(acc[nf], al, &wh[nf >> 1][(nf & 1) * 2]);
            }
        }
    };

    issue_tile(blockIdx.x * 64, 0);
    int cur = 0;
    for (int t = blockIdx.x; t < NT64; t += gridDim.x) {
        CP_WAIT0();
        __syncthreads();                 // X[cur] ready

        uint32_t xh = OFF_X + cur * 36864;
        uint32_t xl = xh + 18432;
        float acc[4][4];
        pass(xh, xl, OFF_W1H, OFF_W1L, acc);
        __syncthreads();                 // all warps done reading X[cur]

        int next = t + gridDim.x;
        if (next < NT64) issue_tile(next * 64, cur ^ 1);  // prefetch into other buf

        // epilogue1: h = relu(acc + b1) -> Y (aliases X[cur])
        int lr0 = warpM * 16 + (lane >> 2);
#pragma unroll
        for (int half = 0; half < 2; half++) {
            int lrow = lr0 + half * 8;
#pragma unroll
            for (int nf = 0; nf < 4; nf++) {
                int col = warpN * 32 + nf * 8 + 2 * (lane & 3);
                float v0 = fmaxf(acc[nf][half * 2 + 0] + b1_s[col], 0.f);
                float v1 = fmaxf(acc[nf][half * 2 + 1] + b1_s[col + 1], 0.f);
                uint32_t h, l;
                split2(v0, v1, h, l);
                int c = col >> 6, cc = col & 63;
                uint32_t off = c * C64 + lrow * RSTRIDE + cc * 2;
                *(uint32_t*)(smem + xh + off) = h;
                *(uint32_t*)(smem + xl + off) = l;
            }
        }
        __syncthreads();                 // Y complete

        pass(xh, xl, OFF_W2H, OFF_W2L, acc);

        // epilogue2: out = acc + b2 (fp32 stats, fp16 store)
        int r0 = t * 64 + lr0;
#pragma unroll
        for (int half = 0; half < 2; half++) {
            int row = r0 + half * 8;
            if (row >= NA) continue;
#pragma unroll
            for (int nf = 0; nf < 4; nf++) {
                int col = warpN * 32 + nf * 8 + 2 * (lane & 3);
                float v0 = acc[nf][half * 2 + 0] + b2_s[col];
                float v1 = acc[nf][half * 2 + 1] + b2_s[col + 1];
                colSum[nf * 2] += v0;     colSq[nf * 2] += v0 * v0;
                colSum[nf * 2 + 1] += v1; colSq[nf * 2 + 1] += v1 * v1;
                __half2 p = __floats2half2_rn(v0, v1);
                *(uint32_t*)(C16 + row * HID + col) = *(uint32_t*)&p;
            }
        }
        cur ^= 1;
    }

    // stats reduction
    __syncthreads();
    float* rs = (float*)smem;
    if (tid < 256) rs[tid] = 0.f;
    __syncthreads();
#pragma unroll
    for (int j = 0; j < 8; j++) {
        int col = warpN * 32 + (j >> 1) * 8 + 2 * (lane & 3) + (j & 1);
        atomicAdd(&rs[col], colSum[j]);
        atomicAdd(&rs[128 + col], colSq[j]);
    }
    __syncthreads();
    if (tid < 128) {
        atomicAdd(&g_sumA[slot][tid], rs[tid]);
        atomicAdd(&g_sumsqA[slot][tid], rs[128 + tid]);
    }
}

// ====================== pooling (+fused BN/ReLU of last depth) =============
__global__ void pool_kernel(const int* __restrict__ seg, float* __restrict__ out,
                            const float* __restrict__ gamma,
                            const float* __restrict__ beta, int slot) {
    int m = blockIdx.x;
    int t = threadIdx.x;
    const float invN = 1.f / (float)NA;
    float mean = g_sumA[slot][t] * invN;
    float var = g_sumsqA[slot][t] * invN - mean * mean;
    float sc = gamma[t] * rsqrtf(var + 1e-5f);
    float sh = beta[t] - mean * sc;
    int lo = 0, hi = NA;
    while (lo < hi) { int mid = (lo + hi) >> 1; if (seg[mid] < m) lo = mid + 1; else hi = mid; }
    int start = lo;
    hi = NA;
    while (lo < hi) { int mid = (lo + hi) >> 1; if (seg[mid] < m + 1) lo = mid + 1; else hi = mid; }
    int end = lo;
    float s = 0.f;
    for (int a = start; a < end; a++) {
        float v = __half2float(g_aggh[a * HID + t]);
        s += fmaxf(fmaf(v, sc, sh), 0.f);
    }
    int cnt = end - start;
    out[m * HID + t] = (cnt > 0) ? s / (float)cnt : 0.f;
}

// ====================== launch ======================
extern "C" void kernel_launch(void* const* d_in, const int* in_sizes, int n_in,
                              void* d_out, int out_size) {
    const float* f_atoms = (const float*)d_in[0];
    const float* W_in    = (const float*)d_in[1];
    const float* b_in    = (const float*)d_in[2];
    const float* W1      = (const float*)d_in[3];
    const float* b1      = (const float*)d_in[4];
    const float* W2      = (const float*)d_in[5];
    const float* b2      = (const float*)d_in[6];
    const float* gamma   = (const float*)d_in[7];
    const float* beta    = (const float*)d_in[8];
    const float* epsp    = (const float*)d_in[9];
    const int*   ei      = (const int*)d_in[10];
    const int*   seg     = (const int*)d_in[11];
    float* out = (float*)d_out;

    __half *p_xh, *p_aggh;
    __nv_bfloat16 *p_fh, *p_fl, *p_ah, *p_al;
    __nv_bfloat16 *p_wfh, *p_wfl, *p_w1h, *p_w1l, *p_w2h, *p_w2l;
    cudaGetSymbolAddress((void**)&p_xh, g_xh);
    cudaGetSymbolAddress((void**)&p_aggh, g_aggh);
    cudaGetSymbolAddress((void**)&p_fh, g_fh);
    cudaGetSymbolAddress((void**)&p_fl, g_fl);
    cudaGetSymbolAddress((void**)&p_ah, g_ah);
    cudaGetSymbolAddress((void**)&p_al, g_al);
    cudaGetSymbolAddress((void**)&p_wfh, g_wfh);
    cudaGetSymbolAddress((void**)&p_wfl, g_wfl);
    cudaGetSymbolAddress((void**)&p_w1h, g_w1h);
    cudaGetSymbolAddress((void**)&p_w1l, g_w1l);
    cudaGetSymbolAddress((void**)&p_w2h, g_w2h);
    cudaGetSymbolAddress((void**)&p_w2l, g_w2l);

    const int SMEM_IN  = 512 + 6 * WCHUNK + 2 * 55296;   // 221696
    const int SMEM_MLP = 1024 + 8 * WCHUNK + 2 * 36864;  // 222208
    cudaFuncSetAttribute(gemm_in_kernel,
                         cudaFuncAttributeMaxDynamicSharedMemorySize, SMEM_IN);
    cudaFuncSetAttribute(mlp_fused_kernel,
                         cudaFuncAttributeMaxDynamicSharedMemorySize, SMEM_MLP);

    const int EDGE4_BLOCKS = (NE / 4 + 255) / 256;

    prep_weights_kernel<<<96, 256>>>(W_in, W1, W2);
    convert_atoms_kernel<<<(NA * (KPAD / 2) + 255) / 256, 256>>>(f_atoms);
    zero_csr_kernel<<<98, 1024>>>();
    gemm_in_kernel<<<148, GTHREADS, SMEM_IN>>>(p_fh, p_fl, p_wfh, p_wfl, b_in, p_xh);
    count_kernel<<<EDGE4_BLOCKS, 256>>>(ei);
    scan_kernel<<<1, 1024>>>();
    fill_kernel<<<EDGE4_BLOCKS, 256>>>(ei);

    for (int d = 0; d < 3; d++) {
        int rslot = (d + 1) & 1;
        int zslot = d & 1;
        if (d == 0)
            gather_kernel<false><<<(NA + 7) / 8, 256>>>(p_xh, epsp, d, nullptr, nullptr, 0, zslot);
        else
            gather_kernel<true><<<(NA + 7) / 8, 256>>>(p_aggh, epsp, d,
                gamma + (d - 1) * HID, beta + (d - 1) * HID, rslot, zslot);
        mlp_fused_kernel<<<148, GTHREADS, SMEM_MLP>>>(
            p_ah, p_al,
            p_w1h + d * HID * HID, p_w1l + d * HID * HID,
            p_w2h + d * HID * HID, p_w2l + d * HID * HID,
            b1 + d * HID, b2 + d * HID, p_aggh, zslot);
    }

    pool_kernel<<<NM, HID>>>(seg, out, gamma + 2 * HID, beta + 2 * HID, 0);
}